// round 6
// baseline (speedup 1.0000x reference)
#include <cuda_runtime.h>
#include <cstdint>

// ---------------- problem constants ----------------
#define B_    8
#define CIN   128
#define COUT  128
#define NPTS  8192
#define KM    32
#define MODES 256
#define SPLIT1 16
#define KC    64          // K per chunk (fp32 elems)
#define NT_   128         // N tile
#define NTHR  512

// ---------------- device scratch ----------------
__device__ float g_part[SPLIT1 * B_ * CIN * MODES];   // 16.8 MB
__device__ float g_W2[CIN * COUT * MODES];            // 16.8 MB
__device__ float g_yhat[B_ * COUT * MODES];           // 1 MB
__device__ float g_warm[32];

__device__ __forceinline__ uint32_t smem_u32(const void* p) {
    uint32_t a;
    asm("{ .reg .u64 t; cvta.to.shared.u64 t, %1; cvt.u32.u64 %0, t; }" : "=r"(a) : "l"(p));
    return a;
}
__device__ __forceinline__ uint32_t pk_bf16(float lo, float hi) {
    uint32_t r;
    asm("cvt.rn.bf16x2.f32 %0, %1, %2;" : "=r"(r) : "f"(hi), "f"(lo));
    return r;
}
// convert 8 consecutive fp32 to hi/lo bf16, store 16B each at hiA/loA
__device__ __forceinline__ void cvt_store8(uint32_t hiA, uint32_t loA, float4 v0, float4 v1) {
    uint32_t h0 = pk_bf16(v0.x, v0.y);
    uint32_t h1 = pk_bf16(v0.z, v0.w);
    uint32_t h2 = pk_bf16(v1.x, v1.y);
    uint32_t h3 = pk_bf16(v1.z, v1.w);
    float r0 = v0.x - __uint_as_float(h0 << 16);
    float r1 = v0.y - __uint_as_float(h0 & 0xffff0000u);
    float r2 = v0.z - __uint_as_float(h1 << 16);
    float r3 = v0.w - __uint_as_float(h1 & 0xffff0000u);
    float r4 = v1.x - __uint_as_float(h2 << 16);
    float r5 = v1.y - __uint_as_float(h2 & 0xffff0000u);
    float r6 = v1.z - __uint_as_float(h3 << 16);
    float r7 = v1.w - __uint_as_float(h3 & 0xffff0000u);
    uint32_t l0 = pk_bf16(r0, r1), l1 = pk_bf16(r2, r3);
    uint32_t l2 = pk_bf16(r4, r5), l3 = pk_bf16(r6, r7);
    asm volatile("st.shared.v4.b32 [%0], {%1,%2,%3,%4};" :: "r"(hiA), "r"(h0), "r"(h1), "r"(h2), "r"(h3));
    asm volatile("st.shared.v4.b32 [%0], {%1,%2,%3,%4};" :: "r"(loA), "r"(l0), "r"(l1), "r"(l2), "r"(l3));
}

#define LDSM4(r, addr) \
    asm volatile("ldmatrix.sync.aligned.m8n8.x4.shared.b16 {%0,%1,%2,%3}, [%4];" \
        : "=r"((r)[0]), "=r"((r)[1]), "=r"((r)[2]), "=r"((r)[3]) : "r"(addr))
#define LDSM4T(r, addr) \
    asm volatile("ldmatrix.sync.aligned.m8n8.x4.trans.shared.b16 {%0,%1,%2,%3}, [%4];" \
        : "=r"((r)[0]), "=r"((r)[1]), "=r"((r)[2]), "=r"((r)[3]) : "r"(addr))
#define MMA(c, a, bq) \
    asm volatile("mma.sync.aligned.m16n8k16.row.col.f32.bf16.bf16.f32 " \
        "{%0,%1,%2,%3}, {%4,%5,%6,%7}, {%8,%9}, {%0,%1,%2,%3};" \
        : "+f"((c)[0]), "+f"((c)[1]), "+f"((c)[2]), "+f"((c)[3]) \
        : "r"((a)[0]), "r"((a)[1]), "r"((a)[2]), "r"((a)[3]), "r"((bq)[0]), "r"((bq)[1]))

// ===========================================================================
// GEMM variant NT (stage 3): both A and B rows K-contiguous. (unchanged)
// ===========================================================================
#define RSTR   144
#define ABYT   (128 * RSTR)                    // 18432
#define NT_OFF_AH 0
#define NT_OFF_AL (ABYT)
#define NT_OFF_BH (2 * ABYT)
#define NT_OFF_BL (3 * ABYT)
#define NT_STAGE  (4 * ABYT)                   // 73728
#define NT_SMEM   (2 * NT_STAGE)               // 147456

__global__ __launch_bounds__(NTHR, 1) void gemm_nt(
    const float* __restrict__ A, const float* __restrict__ B, float* __restrict__ C,
    int lda, int ldb, int ldc,
    long sA, long sB, long sCb, int nChunks)
{
    extern __shared__ __align__(16) char smem[];
    const uint32_t sb = smem_u32(smem);
    const int tid = threadIdx.x, wid = tid >> 5, lane = tid & 31;
    const int nt = blockIdx.x, b = blockIdx.z;

    const float* Ab = A + (long)b * sA;
    const float* Bb = B + (long)b * sB + (long)nt * NT_ * ldb;
    float* Cb = C + (long)b * sCb + (long)nt * NT_;

    const int srow = tid >> 2, sk = (tid & 3) * 16;
    const float* ag = Ab + (long)srow * lda + sk;
    const float* bg = Bb + (long)srow * ldb + sk;
    const uint32_t sOff = (uint32_t)(srow * RSTR + sk * 2);

    const int wm = wid >> 2, wn = wid & 3;
    const int l16 = lane & 15, lh = lane >> 4;
    const int bn = ((lane >> 4) & 1) * 8 + (lane & 7);
    const int bk = ((lane >> 3) & 1) * 8;

    float c[2][4][4];
#pragma unroll
    for (int i = 0; i < 2; i++)
#pragma unroll
        for (int j = 0; j < 4; j++)
#pragma unroll
            for (int q = 0; q < 4; q++) c[i][j][q] = 0.f;

    float4 av[4], bv[4];
#pragma unroll
    for (int g = 0; g < 4; g++) { av[g] = *(const float4*)(ag + g * 4); bv[g] = *(const float4*)(bg + g * 4); }
    cvt_store8(sb + NT_OFF_AH + sOff,      sb + NT_OFF_AL + sOff,      av[0], av[1]);
    cvt_store8(sb + NT_OFF_AH + sOff + 16, sb + NT_OFF_AL + sOff + 16, av[2], av[3]);
    cvt_store8(sb + NT_OFF_BH + sOff,      sb + NT_OFF_BL + sOff,      bv[0], bv[1]);
    cvt_store8(sb + NT_OFF_BH + sOff + 16, sb + NT_OFF_BL + sOff + 16, bv[2], bv[3]);

    for (int i = 0; i < nChunks; i++) {
        __syncthreads();
        const int cur = i & 1;
        const bool more = (i + 1 < nChunks);
        if (more) {
            const float* ag2 = ag + (long)(i + 1) * KC;
            const float* bg2 = bg + (long)(i + 1) * KC;
#pragma unroll
            for (int g = 0; g < 4; g++) { av[g] = *(const float4*)(ag2 + g * 4); bv[g] = *(const float4*)(bg2 + g * 4); }
        }
        const uint32_t base = sb + (uint32_t)(cur * NT_STAGE);
#pragma unroll
        for (int h = 0; h < 4; h++) {
            uint32_t ahi[2][4], alo[2][4], bf[4][2];
            const uint32_t aAddr = base + NT_OFF_AH + (uint32_t)((wm * 32 + l16) * RSTR + (h * 16 + lh * 8) * 2);
            LDSM4(ahi[0], aAddr);
            LDSM4(ahi[1], aAddr + 16 * RSTR);
            LDSM4(alo[0], aAddr + ABYT);
            LDSM4(alo[1], aAddr + ABYT + 16 * RSTR);
            const uint32_t bAddr = base + NT_OFF_BH + (uint32_t)((wn * 32 + bn) * RSTR + (h * 16 + bk) * 2);
            LDSM4(bf[0], bAddr);
            LDSM4(bf[2], bAddr + 16 * RSTR);
#pragma unroll
            for (int mt = 0; mt < 2; mt++)
#pragma unroll
                for (int nn = 0; nn < 4; nn++) {
                    MMA(c[mt][nn], ahi[mt], (&bf[0][0]) + nn * 2);
                    MMA(c[mt][nn], alo[mt], (&bf[0][0]) + nn * 2);
                }
            LDSM4(bf[0], bAddr + ABYT);
            LDSM4(bf[2], bAddr + ABYT + 16 * RSTR);
#pragma unroll
            for (int mt = 0; mt < 2; mt++)
#pragma unroll
                for (int nn = 0; nn < 4; nn++)
                    MMA(c[mt][nn], ahi[mt], (&bf[0][0]) + nn * 2);
        }
        if (more) {
            const uint32_t nb = sb + (uint32_t)(((i + 1) & 1) * NT_STAGE);
            cvt_store8(nb + NT_OFF_AH + sOff,      nb + NT_OFF_AL + sOff,      av[0], av[1]);
            cvt_store8(nb + NT_OFF_AH + sOff + 16, nb + NT_OFF_AL + sOff + 16, av[2], av[3]);
            cvt_store8(nb + NT_OFF_BH + sOff,      nb + NT_OFF_BL + sOff,      bv[0], bv[1]);
            cvt_store8(nb + NT_OFF_BH + sOff + 16, nb + NT_OFF_BL + sOff + 16, bv[2], bv[3]);
        }
    }

    const int mrow = wm * 32 + (lane >> 2);
    const int ncol = wn * 32 + (lane & 3) * 2;
#pragma unroll
    for (int mt = 0; mt < 2; mt++)
#pragma unroll
        for (int nn = 0; nn < 4; nn++) {
            float* p = Cb + (long)(mrow + mt * 16) * ldc + ncol + nn * 8;
            *(float2*)p = make_float2(c[mt][nn][0], c[mt][nn][1]);
            *(float2*)(p + (long)8 * ldc) = make_float2(c[mt][nn][2], c[mt][nn][3]);
        }
}

// ===========================================================================
// GEMM variant TB (stage 1): A = x (rows K-contiguous, stride NPTS);
// B = wbases [k][modes] staged as-is, fragments via ldmatrix.trans.
// Fixes vs R5: conflict-free B staging (16 thr/row), B-only register prefetch.
// ===========================================================================
#define BRSTR  272                              // 128 modes*2B + 16B pad
#define TB_ABYT (128 * RSTR)                    // 18432 per A half
#define TB_BBYT (KC * BRSTR)                    // 17408 per B half
#define TB_OFF_AH 0
#define TB_OFF_AL (TB_ABYT)
#define TB_OFF_BH (2 * TB_ABYT)
#define TB_OFF_BL (2 * TB_ABYT + TB_BBYT)
#define TB_STAGE  (2 * TB_ABYT + 2 * TB_BBYT)   // 71680
#define TB_SMEM   (2 * TB_STAGE)                // 143360

__global__ __launch_bounds__(NTHR, 1) void gemm_tb(
    const float* __restrict__ A, const float* __restrict__ B, float* __restrict__ C,
    int nChunks)
{
    extern __shared__ __align__(16) char smem[];
    const uint32_t sb = smem_u32(smem);
    const int tid = threadIdx.x, wid = tid >> 5, lane = tid & 31;
    const int nt = blockIdx.x, sp = blockIdx.y, b = blockIdx.z;
    const long k0 = (long)sp * nChunks * KC;

    const float* Ab = A + (long)b * CIN * NPTS + k0;                       // x
    const float* Bb = B + (long)b * NPTS * MODES + k0 * MODES + nt * NT_;  // wbases
    float* Cb = C + ((long)sp * B_ + b) * CIN * MODES + nt * NT_;          // partials

    // A staging: 128 rows x 64 k, 4 threads/row, loaded at store time (L2-hot)
    const int srow = tid >> 2, sk = (tid & 3) * 16;
    const float* ag = Ab + (long)srow * NPTS + sk;
    const uint32_t aOff = (uint32_t)(srow * RSTR + sk * 2);
    // B staging: 64 k-rows x 128 modes, 16 threads/row (conflict-free STS),
    // each thread covers rows brow and brow+32, 8 floats each. Prefetched.
    const int brow = tid >> 4, bc = (tid & 15) * 8;
    const float* bg = Bb + (long)brow * MODES + bc;
    const uint32_t bOff = (uint32_t)(brow * BRSTR + bc * 2);

    const int wm = wid >> 2, wn = wid & 3;
    const int l16 = lane & 15, lh = lane >> 4;
    const int tkl = ((lane >> 3) & 1) * 8 + (lane & 7);
    const int tnl = (lane >> 4) * 8;

    float c[2][4][4];
#pragma unroll
    for (int i = 0; i < 2; i++)
#pragma unroll
        for (int j = 0; j < 4; j++)
#pragma unroll
            for (int q = 0; q < 4; q++) c[i][j][q] = 0.f;

    float4 bv[4];

    // prologue: chunk 0 -> buffer 0
    {
        float4 av0 = *(const float4*)(ag);
        float4 av1 = *(const float4*)(ag + 4);
        float4 av2 = *(const float4*)(ag + 8);
        float4 av3 = *(const float4*)(ag + 12);
        bv[0] = *(const float4*)(bg);
        bv[1] = *(const float4*)(bg + 4);
        bv[2] = *(const float4*)(bg + (long)32 * MODES);
        bv[3] = *(const float4*)(bg + (long)32 * MODES + 4);
        cvt_store8(sb + TB_OFF_AH + aOff,      sb + TB_OFF_AL + aOff,      av0, av1);
        cvt_store8(sb + TB_OFF_AH + aOff + 16, sb + TB_OFF_AL + aOff + 16, av2, av3);
        cvt_store8(sb + TB_OFF_BH + bOff,      sb + TB_OFF_BL + bOff,      bv[0], bv[1]);
        cvt_store8(sb + TB_OFF_BH + bOff + 32 * BRSTR, sb + TB_OFF_BL + bOff + 32 * BRSTR, bv[2], bv[3]);
    }

    for (int i = 0; i < nChunks; i++) {
        __syncthreads();
        const int cur = i & 1;
        const bool more = (i + 1 < nChunks);
        if (more) {
            // prefetch B (DRAM latency) during the MMA phase
            const float* bg2 = bg + (long)(i + 1) * KC * MODES;
            bv[0] = *(const float4*)(bg2);
            bv[1] = *(const float4*)(bg2 + 4);
            bv[2] = *(const float4*)(bg2 + (long)32 * MODES);
            bv[3] = *(const float4*)(bg2 + (long)32 * MODES + 4);
        }
        const uint32_t base = sb + (uint32_t)(cur * TB_STAGE);
#pragma unroll
        for (int h = 0; h < 4; h++) {
            uint32_t ahi[2][4], alo[2][4], bf[4][2];
            const uint32_t aAddr = base + TB_OFF_AH + (uint32_t)((wm * 32 + l16) * RSTR + (h * 16 + lh * 8) * 2);
            LDSM4(ahi[0], aAddr);
            LDSM4(ahi[1], aAddr + 16 * RSTR);
            LDSM4(alo[0], aAddr + TB_ABYT);
            LDSM4(alo[1], aAddr + TB_ABYT + 16 * RSTR);
            const uint32_t bAddr = base + TB_OFF_BH + (uint32_t)((h * 16 + tkl) * BRSTR + (wn * 32 + tnl) * 2);
            LDSM4T(bf[0], bAddr);            // nn0 (n0-7), nn1 (n8-15)
            LDSM4T(bf[2], bAddr + 16 * 2);   // nn2 (n16-23), nn3 (n24-31)
#pragma unroll
            for (int mt = 0; mt < 2; mt++)
#pragma unroll
                for (int nn = 0; nn < 4; nn++) {
                    MMA(c[mt][nn], ahi[mt], (&bf[0][0]) + nn * 2);
                    MMA(c[mt][nn], alo[mt], (&bf[0][0]) + nn * 2);
                }
            LDSM4T(bf[0], bAddr + TB_BBYT);
            LDSM4T(bf[2], bAddr + TB_BBYT + 16 * 2);
#pragma unroll
            for (int mt = 0; mt < 2; mt++)
#pragma unroll
                for (int nn = 0; nn < 4; nn++)
                    MMA(c[mt][nn], ahi[mt], (&bf[0][0]) + nn * 2);
        }
        if (more) {
            const uint32_t nb = sb + (uint32_t)(((i + 1) & 1) * TB_STAGE);
            // A loaded now (x is L2-resident), stored immediately
            const float* ag2 = ag + (long)(i + 1) * KC;
            float4 av0 = *(const float4*)(ag2);
            float4 av1 = *(const float4*)(ag2 + 4);
            float4 av2 = *(const float4*)(ag2 + 8);
            float4 av3 = *(const float4*)(ag2 + 12);
            cvt_store8(nb + TB_OFF_AH + aOff,      nb + TB_OFF_AL + aOff,      av0, av1);
            cvt_store8(nb + TB_OFF_AH + aOff + 16, nb + TB_OFF_AL + aOff + 16, av2, av3);
            cvt_store8(nb + TB_OFF_BH + bOff,      nb + TB_OFF_BL + bOff,      bv[0], bv[1]);
            cvt_store8(nb + TB_OFF_BH + bOff + 32 * BRSTR, nb + TB_OFF_BL + bOff + 32 * BRSTR, bv[2], bv[3]);
        }
    }

    const int mrow = wm * 32 + (lane >> 2);
    const int ncol = wn * 32 + (lane & 3) * 2;
#pragma unroll
    for (int mt = 0; mt < 2; mt++)
#pragma unroll
        for (int nn = 0; nn < 4; nn++) {
            float* p = Cb + (long)(mrow + mt * 16) * MODES + ncol + nn * 8;
            *(float2*)p = make_float2(c[mt][nn][0], c[mt][nn][1]);
            *(float2*)(p + (long)8 * MODES) = make_float2(c[mt][nn][2], c[mt][nn][3]);
        }
}

// W2[r,k] = sum_j weights[r,j] * D[j,k]
__global__ __launch_bounds__(256) void k2a_w2(const float* __restrict__ weights,
                                              const float* __restrict__ D) {
    __shared__ float ws[64][KM];
    const int r0 = blockIdx.x * 64;
    const int k  = threadIdx.x;
    for (int idx = threadIdx.x; idx < 64 * KM; idx += 256)
        ws[idx >> 5][idx & 31] = weights[(size_t)r0 * KM + idx];
    float Dreg[KM];
#pragma unroll
    for (int j = 0; j < KM; j++) Dreg[j] = D[(size_t)j * MODES + k];
    __syncthreads();
    for (int r = 0; r < 64; r++) {
        float acc = 0.f;
#pragma unroll
        for (int j = 0; j < KM; j++) acc += ws[r][j] * Dreg[j];
        g_W2[(size_t)(r0 + r) * MODES + k] = acc;
    }
}

// Fused split-K reduce + channel mixing.
__global__ __launch_bounds__(256) void k2b_fused() {
    const int k = blockIdx.x;
    __shared__ float xs[B_][CIN];   // 4 KB
    for (int idx = threadIdx.x; idx < B_ * CIN; idx += 256) {
        float s = 0.f;
#pragma unroll
        for (int p = 0; p < SPLIT1; p++)
            s += g_part[(size_t)p * (B_ * CIN * MODES) + (size_t)idx * MODES + k];
        xs[idx >> 7][idx & 127] = s;
    }
    __syncthreads();
    const int o  = threadIdx.x & 127;
    const int bh = (threadIdx.x >> 7) * 4;
    float acc[4] = {0.f, 0.f, 0.f, 0.f};
#pragma unroll 4
    for (int i = 0; i < CIN; i++) {
        const float w = g_W2[((size_t)i * COUT + o) * MODES + k];
#pragma unroll
        for (int bb = 0; bb < 4; bb++) acc[bb] += xs[bh + bb][i] * w;
    }
#pragma unroll
    for (int bb = 0; bb < 4; bb++)
        g_yhat[((size_t)(bh + bb) * COUT + o) * MODES + k] = acc[bb];
}

// tiny deterministic warm kernels (launch-order alignment for profiling)
__global__ void warm1() { if (threadIdx.x < 32) g_warm[threadIdx.x] = 0.f; }
__global__ void warm2() { if (threadIdx.x < 32) g_warm[threadIdx.x] = 1.f; }

// ---------------------------------------------------------------------------
extern "C" void kernel_launch(void* const* d_in, const int* in_sizes, int n_in,
                              void* d_out, int out_size) {
    const float* x       = (const float*)d_in[0];   // (8, 128, 8192)
    const float* wbases  = (const float*)d_in[1];   // (8, 8192, 256)
    const float* bases   = (const float*)d_in[2];   // (8, 8192, 256)
    const float* weights = (const float*)d_in[3];   // (128, 128, 32)
    const float* Dm      = (const float*)d_in[4];   // (32, 256)
    float* y = (float*)d_out;                       // (8, 128, 8192)

    cudaFuncSetAttribute(gemm_nt, cudaFuncAttributeMaxDynamicSharedMemorySize, NT_SMEM);
    cudaFuncSetAttribute(gemm_tb, cudaFuncAttributeMaxDynamicSharedMemorySize, TB_SMEM);

    void *p_part, *p_yhat;
    cudaGetSymbolAddress(&p_part, g_part);
    cudaGetSymbolAddress(&p_yhat, g_yhat);

    // (1) W2 precompute  (2,3) warm no-ops so gemm_tb is the 4th launch
    k2a_w2<<<CIN * COUT / 64, 256>>>(weights, Dm);
    warm1<<<1, 32>>>();
    warm2<<<1, 32>>>();

    // (4) Stage 1: x_hat partials = x @ wbases  (split-K=16 -> 256 CTAs)
    gemm_tb<<<dim3(MODES / NT_, SPLIT1, B_), NTHR, TB_SMEM>>>(
        x, wbases, (float*)p_part, (NPTS / SPLIT1) / KC);   // 8 chunks

    // (5) Stage 2: fused reduce + channel mixing
    k2b_fused<<<MODES, 256>>>();

    // (6) Stage 3: y = y_hat @ bases^T  (512 CTAs)
    gemm_nt<<<dim3(NPTS / NT_, 1, B_), NTHR, NT_SMEM>>>(
        (const float*)p_yhat, bases, y,
        MODES, MODES, NPTS,
        (long)COUT * MODES, (long)NPTS * MODES, (long)CIN * NPTS,
        MODES / KC);                                        // 4 chunks
}

// round 7
// speedup vs baseline: 1.3087x; 1.3087x over previous
#include <cuda_runtime.h>
#include <cstdint>

// ---------------- problem constants ----------------
#define B_    8
#define CIN   128
#define COUT  128
#define NPTS  8192
#define KM    32
#define MODES 256
#define SPLIT1 16
#define KC    64          // K per chunk (fp32 elems)
#define NT_   128         // N tile
#define NTHR  512
#define IGRP  8           // i-groups for stage-2 split

// ---------------- device scratch ----------------
__device__ float g_part[SPLIT1 * B_ * CIN * MODES];   // 16.8 MB
__device__ float g_xhat[B_ * CIN * MODES];            // 1 MB
__device__ float g_W2[CIN * COUT * MODES];            // 16.8 MB
__device__ float g_part2[IGRP * B_ * COUT * MODES];   // 8.4 MB
__device__ float g_yhat[B_ * COUT * MODES];           // 1 MB

__device__ __forceinline__ uint32_t smem_u32(const void* p) {
    uint32_t a;
    asm("{ .reg .u64 t; cvta.to.shared.u64 t, %1; cvt.u32.u64 %0, t; }" : "=r"(a) : "l"(p));
    return a;
}
__device__ __forceinline__ uint32_t pk_bf16(float lo, float hi) {
    uint32_t r;
    asm("cvt.rn.bf16x2.f32 %0, %1, %2;" : "=r"(r) : "f"(hi), "f"(lo));
    return r;
}
// convert 8 consecutive fp32 to hi/lo bf16, store 16B each at hiA/loA
__device__ __forceinline__ void cvt_store8(uint32_t hiA, uint32_t loA, float4 v0, float4 v1) {
    uint32_t h0 = pk_bf16(v0.x, v0.y);
    uint32_t h1 = pk_bf16(v0.z, v0.w);
    uint32_t h2 = pk_bf16(v1.x, v1.y);
    uint32_t h3 = pk_bf16(v1.z, v1.w);
    float r0 = v0.x - __uint_as_float(h0 << 16);
    float r1 = v0.y - __uint_as_float(h0 & 0xffff0000u);
    float r2 = v0.z - __uint_as_float(h1 << 16);
    float r3 = v0.w - __uint_as_float(h1 & 0xffff0000u);
    float r4 = v1.x - __uint_as_float(h2 << 16);
    float r5 = v1.y - __uint_as_float(h2 & 0xffff0000u);
    float r6 = v1.z - __uint_as_float(h3 << 16);
    float r7 = v1.w - __uint_as_float(h3 & 0xffff0000u);
    uint32_t l0 = pk_bf16(r0, r1), l1 = pk_bf16(r2, r3);
    uint32_t l2 = pk_bf16(r4, r5), l3 = pk_bf16(r6, r7);
    asm volatile("st.shared.v4.b32 [%0], {%1,%2,%3,%4};" :: "r"(hiA), "r"(h0), "r"(h1), "r"(h2), "r"(h3));
    asm volatile("st.shared.v4.b32 [%0], {%1,%2,%3,%4};" :: "r"(loA), "r"(l0), "r"(l1), "r"(l2), "r"(l3));
}

#define LDSM4(r, addr) \
    asm volatile("ldmatrix.sync.aligned.m8n8.x4.shared.b16 {%0,%1,%2,%3}, [%4];" \
        : "=r"((r)[0]), "=r"((r)[1]), "=r"((r)[2]), "=r"((r)[3]) : "r"(addr))
#define LDSM4T(r, addr) \
    asm volatile("ldmatrix.sync.aligned.m8n8.x4.trans.shared.b16 {%0,%1,%2,%3}, [%4];" \
        : "=r"((r)[0]), "=r"((r)[1]), "=r"((r)[2]), "=r"((r)[3]) : "r"(addr))
#define MMA(c, a, bq) \
    asm volatile("mma.sync.aligned.m16n8k16.row.col.f32.bf16.bf16.f32 " \
        "{%0,%1,%2,%3}, {%4,%5,%6,%7}, {%8,%9}, {%0,%1,%2,%3};" \
        : "+f"((c)[0]), "+f"((c)[1]), "+f"((c)[2]), "+f"((c)[3]) \
        : "r"((a)[0]), "r"((a)[1]), "r"((a)[2]), "r"((a)[3]), "r"((bq)[0]), "r"((bq)[1]))

// ===========================================================================
// GEMM variant NT (stage 3): both A and B rows K-contiguous. (unchanged)
// ===========================================================================
#define RSTR   144
#define ABYT   (128 * RSTR)                    // 18432
#define NT_OFF_AH 0
#define NT_OFF_AL (ABYT)
#define NT_OFF_BH (2 * ABYT)
#define NT_OFF_BL (3 * ABYT)
#define NT_STAGE  (4 * ABYT)                   // 73728
#define NT_SMEM   (2 * NT_STAGE)               // 147456

__global__ __launch_bounds__(NTHR, 1) void gemm_nt(
    const float* __restrict__ A, const float* __restrict__ B, float* __restrict__ C,
    int lda, int ldb, int ldc,
    long sA, long sB, long sCb, int nChunks)
{
    extern __shared__ __align__(16) char smem[];
    const uint32_t sb = smem_u32(smem);
    const int tid = threadIdx.x, wid = tid >> 5, lane = tid & 31;
    const int nt = blockIdx.x, b = blockIdx.z;

    const float* Ab = A + (long)b * sA;
    const float* Bb = B + (long)b * sB + (long)nt * NT_ * ldb;
    float* Cb = C + (long)b * sCb + (long)nt * NT_;

    const int srow = tid >> 2, sk = (tid & 3) * 16;
    const float* ag = Ab + (long)srow * lda + sk;
    const float* bg = Bb + (long)srow * ldb + sk;
    const uint32_t sOff = (uint32_t)(srow * RSTR + sk * 2);

    const int wm = wid >> 2, wn = wid & 3;
    const int l16 = lane & 15, lh = lane >> 4;
    const int bn = ((lane >> 4) & 1) * 8 + (lane & 7);
    const int bk = ((lane >> 3) & 1) * 8;

    float c[2][4][4];
#pragma unroll
    for (int i = 0; i < 2; i++)
#pragma unroll
        for (int j = 0; j < 4; j++)
#pragma unroll
            for (int q = 0; q < 4; q++) c[i][j][q] = 0.f;

    float4 av[4], bv[4];
#pragma unroll
    for (int g = 0; g < 4; g++) { av[g] = *(const float4*)(ag + g * 4); bv[g] = *(const float4*)(bg + g * 4); }
    cvt_store8(sb + NT_OFF_AH + sOff,      sb + NT_OFF_AL + sOff,      av[0], av[1]);
    cvt_store8(sb + NT_OFF_AH + sOff + 16, sb + NT_OFF_AL + sOff + 16, av[2], av[3]);
    cvt_store8(sb + NT_OFF_BH + sOff,      sb + NT_OFF_BL + sOff,      bv[0], bv[1]);
    cvt_store8(sb + NT_OFF_BH + sOff + 16, sb + NT_OFF_BL + sOff + 16, bv[2], bv[3]);

    for (int i = 0; i < nChunks; i++) {
        __syncthreads();
        const int cur = i & 1;
        const bool more = (i + 1 < nChunks);
        if (more) {
            const float* ag2 = ag + (long)(i + 1) * KC;
            const float* bg2 = bg + (long)(i + 1) * KC;
#pragma unroll
            for (int g = 0; g < 4; g++) { av[g] = *(const float4*)(ag2 + g * 4); bv[g] = *(const float4*)(bg2 + g * 4); }
        }
        const uint32_t base = sb + (uint32_t)(cur * NT_STAGE);
#pragma unroll
        for (int h = 0; h < 4; h++) {
            uint32_t ahi[2][4], alo[2][4], bf[4][2];
            const uint32_t aAddr = base + NT_OFF_AH + (uint32_t)((wm * 32 + l16) * RSTR + (h * 16 + lh * 8) * 2);
            LDSM4(ahi[0], aAddr);
            LDSM4(ahi[1], aAddr + 16 * RSTR);
            LDSM4(alo[0], aAddr + ABYT);
            LDSM4(alo[1], aAddr + ABYT + 16 * RSTR);
            const uint32_t bAddr = base + NT_OFF_BH + (uint32_t)((wn * 32 + bn) * RSTR + (h * 16 + bk) * 2);
            LDSM4(bf[0], bAddr);
            LDSM4(bf[2], bAddr + 16 * RSTR);
#pragma unroll
            for (int mt = 0; mt < 2; mt++)
#pragma unroll
                for (int nn = 0; nn < 4; nn++) {
                    MMA(c[mt][nn], ahi[mt], (&bf[0][0]) + nn * 2);
                    MMA(c[mt][nn], alo[mt], (&bf[0][0]) + nn * 2);
                }
            LDSM4(bf[0], bAddr + ABYT);
            LDSM4(bf[2], bAddr + ABYT + 16 * RSTR);
#pragma unroll
            for (int mt = 0; mt < 2; mt++)
#pragma unroll
                for (int nn = 0; nn < 4; nn++)
                    MMA(c[mt][nn], ahi[mt], (&bf[0][0]) + nn * 2);
        }
        if (more) {
            const uint32_t nb = sb + (uint32_t)(((i + 1) & 1) * NT_STAGE);
            cvt_store8(nb + NT_OFF_AH + sOff,      nb + NT_OFF_AL + sOff,      av[0], av[1]);
            cvt_store8(nb + NT_OFF_AH + sOff + 16, nb + NT_OFF_AL + sOff + 16, av[2], av[3]);
            cvt_store8(nb + NT_OFF_BH + sOff,      nb + NT_OFF_BL + sOff,      bv[0], bv[1]);
            cvt_store8(nb + NT_OFF_BH + sOff + 16, nb + NT_OFF_BL + sOff + 16, bv[2], bv[3]);
        }
    }

    const int mrow = wm * 32 + (lane >> 2);
    const int ncol = wn * 32 + (lane & 3) * 2;
#pragma unroll
    for (int mt = 0; mt < 2; mt++)
#pragma unroll
        for (int nn = 0; nn < 4; nn++) {
            float* p = Cb + (long)(mrow + mt * 16) * ldc + ncol + nn * 8;
            *(float2*)p = make_float2(c[mt][nn][0], c[mt][nn][1]);
            *(float2*)(p + (long)8 * ldc) = make_float2(c[mt][nn][2], c[mt][nn][3]);
        }
}

// ===========================================================================
// GEMM variant TB (stage 1): unchanged from R6 (57.6 us measured).
// ===========================================================================
#define BRSTR  272                              // 128 modes*2B + 16B pad
#define TB_ABYT (128 * RSTR)                    // 18432 per A half
#define TB_BBYT (KC * BRSTR)                    // 17408 per B half
#define TB_OFF_AH 0
#define TB_OFF_AL (TB_ABYT)
#define TB_OFF_BH (2 * TB_ABYT)
#define TB_OFF_BL (2 * TB_ABYT + TB_BBYT)
#define TB_STAGE  (2 * TB_ABYT + 2 * TB_BBYT)   // 71680
#define TB_SMEM   (2 * TB_STAGE)                // 143360

__global__ __launch_bounds__(NTHR, 1) void gemm_tb(
    const float* __restrict__ A, const float* __restrict__ B, float* __restrict__ C,
    int nChunks)
{
    extern __shared__ __align__(16) char smem[];
    const uint32_t sb = smem_u32(smem);
    const int tid = threadIdx.x, wid = tid >> 5, lane = tid & 31;
    const int nt = blockIdx.x, sp = blockIdx.y, b = blockIdx.z;
    const long k0 = (long)sp * nChunks * KC;

    const float* Ab = A + (long)b * CIN * NPTS + k0;
    const float* Bb = B + (long)b * NPTS * MODES + k0 * MODES + nt * NT_;
    float* Cb = C + ((long)sp * B_ + b) * CIN * MODES + nt * NT_;

    const int srow = tid >> 2, sk = (tid & 3) * 16;
    const float* ag = Ab + (long)srow * NPTS + sk;
    const uint32_t aOff = (uint32_t)(srow * RSTR + sk * 2);
    const int brow = tid >> 4, bc = (tid & 15) * 8;
    const float* bg = Bb + (long)brow * MODES + bc;
    const uint32_t bOff = (uint32_t)(brow * BRSTR + bc * 2);

    const int wm = wid >> 2, wn = wid & 3;
    const int l16 = lane & 15, lh = lane >> 4;
    const int tkl = ((lane >> 3) & 1) * 8 + (lane & 7);
    const int tnl = (lane >> 4) * 8;

    float c[2][4][4];
#pragma unroll
    for (int i = 0; i < 2; i++)
#pragma unroll
        for (int j = 0; j < 4; j++)
#pragma unroll
            for (int q = 0; q < 4; q++) c[i][j][q] = 0.f;

    float4 bv[4];
    {
        float4 av0 = *(const float4*)(ag);
        float4 av1 = *(const float4*)(ag + 4);
        float4 av2 = *(const float4*)(ag + 8);
        float4 av3 = *(const float4*)(ag + 12);
        bv[0] = *(const float4*)(bg);
        bv[1] = *(const float4*)(bg + 4);
        bv[2] = *(const float4*)(bg + (long)32 * MODES);
        bv[3] = *(const float4*)(bg + (long)32 * MODES + 4);
        cvt_store8(sb + TB_OFF_AH + aOff,      sb + TB_OFF_AL + aOff,      av0, av1);
        cvt_store8(sb + TB_OFF_AH + aOff + 16, sb + TB_OFF_AL + aOff + 16, av2, av3);
        cvt_store8(sb + TB_OFF_BH + bOff,      sb + TB_OFF_BL + bOff,      bv[0], bv[1]);
        cvt_store8(sb + TB_OFF_BH + bOff + 32 * BRSTR, sb + TB_OFF_BL + bOff + 32 * BRSTR, bv[2], bv[3]);
    }

    for (int i = 0; i < nChunks; i++) {
        __syncthreads();
        const int cur = i & 1;
        const bool more = (i + 1 < nChunks);
        if (more) {
            const float* bg2 = bg + (long)(i + 1) * KC * MODES;
            bv[0] = *(const float4*)(bg2);
            bv[1] = *(const float4*)(bg2 + 4);
            bv[2] = *(const float4*)(bg2 + (long)32 * MODES);
            bv[3] = *(const float4*)(bg2 + (long)32 * MODES + 4);
        }
        const uint32_t base = sb + (uint32_t)(cur * TB_STAGE);
#pragma unroll
        for (int h = 0; h < 4; h++) {
            uint32_t ahi[2][4], alo[2][4], bf[4][2];
            const uint32_t aAddr = base + TB_OFF_AH + (uint32_t)((wm * 32 + l16) * RSTR + (h * 16 + lh * 8) * 2);
            LDSM4(ahi[0], aAddr);
            LDSM4(ahi[1], aAddr + 16 * RSTR);
            LDSM4(alo[0], aAddr + TB_ABYT);
            LDSM4(alo[1], aAddr + TB_ABYT + 16 * RSTR);
            const uint32_t bAddr = base + TB_OFF_BH + (uint32_t)((h * 16 + tkl) * BRSTR + (wn * 32 + tnl) * 2);
            LDSM4T(bf[0], bAddr);
            LDSM4T(bf[2], bAddr + 16 * 2);
#pragma unroll
            for (int mt = 0; mt < 2; mt++)
#pragma unroll
                for (int nn = 0; nn < 4; nn++) {
                    MMA(c[mt][nn], ahi[mt], (&bf[0][0]) + nn * 2);
                    MMA(c[mt][nn], alo[mt], (&bf[0][0]) + nn * 2);
                }
            LDSM4T(bf[0], bAddr + TB_BBYT);
            LDSM4T(bf[2], bAddr + TB_BBYT + 16 * 2);
#pragma unroll
            for (int mt = 0; mt < 2; mt++)
#pragma unroll
                for (int nn = 0; nn < 4; nn++)
                    MMA(c[mt][nn], ahi[mt], (&bf[0][0]) + nn * 2);
        }
        if (more) {
            const uint32_t nb = sb + (uint32_t)(((i + 1) & 1) * TB_STAGE);
            const float* ag2 = ag + (long)(i + 1) * KC;
            float4 av0 = *(const float4*)(ag2);
            float4 av1 = *(const float4*)(ag2 + 4);
            float4 av2 = *(const float4*)(ag2 + 8);
            float4 av3 = *(const float4*)(ag2 + 12);
            cvt_store8(nb + TB_OFF_AH + aOff,      nb + TB_OFF_AL + aOff,      av0, av1);
            cvt_store8(nb + TB_OFF_AH + aOff + 16, nb + TB_OFF_AL + aOff + 16, av2, av3);
            cvt_store8(nb + TB_OFF_BH + bOff,      nb + TB_OFF_BL + bOff,      bv[0], bv[1]);
            cvt_store8(nb + TB_OFF_BH + bOff + 32 * BRSTR, nb + TB_OFF_BL + bOff + 32 * BRSTR, bv[2], bv[3]);
        }
    }

    const int mrow = wm * 32 + (lane >> 2);
    const int ncol = wn * 32 + (lane & 3) * 2;
#pragma unroll
    for (int mt = 0; mt < 2; mt++)
#pragma unroll
        for (int nn = 0; nn < 4; nn++) {
            float* p = Cb + (long)(mrow + mt * 16) * MODES + ncol + nn * 8;
            *(float2*)p = make_float2(c[mt][nn][0], c[mt][nn][1]);
            *(float2*)(p + (long)8 * MODES) = make_float2(c[mt][nn][2], c[mt][nn][3]);
        }
}

// W2[r,k] = sum_j weights[r,j] * D[j,k]
__global__ __launch_bounds__(256) void k2a_w2(const float* __restrict__ weights,
                                              const float* __restrict__ D) {
    __shared__ float ws[64][KM];
    const int r0 = blockIdx.x * 64;
    const int k  = threadIdx.x;
    for (int idx = threadIdx.x; idx < 64 * KM; idx += 256)
        ws[idx >> 5][idx & 31] = weights[(size_t)r0 * KM + idx];
    float Dreg[KM];
#pragma unroll
    for (int j = 0; j < KM; j++) Dreg[j] = D[(size_t)j * MODES + k];
    __syncthreads();
    for (int r = 0; r < 64; r++) {
        float acc = 0.f;
#pragma unroll
        for (int j = 0; j < KM; j++) acc += ws[r][j] * Dreg[j];
        g_W2[(size_t)(r0 + r) * MODES + k] = acc;
    }
}

// split-K reduce: x_hat = sum over SPLIT1 partials (float4-vectorized, coalesced)
__global__ __launch_bounds__(256) void k1_reduce() {
    const int i = blockIdx.x * 256 + threadIdx.x;   // float4 index
    const float4* p = (const float4*)g_part;
    float4 s = p[i];
#pragma unroll
    for (int q = 1; q < SPLIT1; q++) {
        float4 v = p[(size_t)q * (B_ * CIN * MODES / 4) + i];
        s.x += v.x; s.y += v.y; s.z += v.z; s.w += v.w;
    }
    ((float4*)g_xhat)[i] = s;
}

// Stage-2 partial: group g covers i in [16g, 16g+16).
//   part2[g][b][o][k] = sum_{i in group} xhat[b][i][k] * W2[i][o][k]
// Grid (32 o-tiles, IGRP groups), 256 threads = k (all accesses coalesced).
__global__ __launch_bounds__(256) void k2b_part() {
    const int o0 = blockIdx.x * 4;
    const int g  = blockIdx.y;
    const int k  = threadIdx.x;
    float acc[B_][4];
#pragma unroll
    for (int b = 0; b < B_; b++)
#pragma unroll
        for (int oo = 0; oo < 4; oo++) acc[b][oo] = 0.f;
    const int i0 = g * (CIN / IGRP);
#pragma unroll
    for (int ii = 0; ii < CIN / IGRP; ii++) {
        const int i = i0 + ii;
        float w[4];
#pragma unroll
        for (int oo = 0; oo < 4; oo++)
            w[oo] = g_W2[((size_t)i * COUT + o0 + oo) * MODES + k];
#pragma unroll
        for (int b = 0; b < B_; b++) {
            const float xv = g_xhat[((size_t)b * CIN + i) * MODES + k];
#pragma unroll
            for (int oo = 0; oo < 4; oo++) acc[b][oo] += xv * w[oo];
        }
    }
#pragma unroll
    for (int b = 0; b < B_; b++)
#pragma unroll
        for (int oo = 0; oo < 4; oo++)
            g_part2[(((size_t)g * B_ + b) * COUT + o0 + oo) * MODES + k] = acc[b][oo];
}

// Final stage-2 reduce: yhat = sum over IGRP groups (float4, coalesced)
__global__ __launch_bounds__(256) void k2b_red2() {
    const int i = blockIdx.x * 256 + threadIdx.x;   // float4 index
    const float4* p = (const float4*)g_part2;
    float4 s = p[i];
#pragma unroll
    for (int q = 1; q < IGRP; q++) {
        float4 v = p[(size_t)q * (B_ * COUT * MODES / 4) + i];
        s.x += v.x; s.y += v.y; s.z += v.z; s.w += v.w;
    }
    ((float4*)g_yhat)[i] = s;
}

// ---------------------------------------------------------------------------
extern "C" void kernel_launch(void* const* d_in, const int* in_sizes, int n_in,
                              void* d_out, int out_size) {
    const float* x       = (const float*)d_in[0];   // (8, 128, 8192)
    const float* wbases  = (const float*)d_in[1];   // (8, 8192, 256)
    const float* bases   = (const float*)d_in[2];   // (8, 8192, 256)
    const float* weights = (const float*)d_in[3];   // (128, 128, 32)
    const float* Dm      = (const float*)d_in[4];   // (32, 256)
    float* y = (float*)d_out;                       // (8, 128, 8192)

    cudaFuncSetAttribute(gemm_nt, cudaFuncAttributeMaxDynamicSharedMemorySize, NT_SMEM);
    cudaFuncSetAttribute(gemm_tb, cudaFuncAttributeMaxDynamicSharedMemorySize, TB_SMEM);

    void *p_part, *p_yhat;
    cudaGetSymbolAddress(&p_part, g_part);
    cudaGetSymbolAddress(&p_yhat, g_yhat);

    // (1) W2 precompute
    k2a_w2<<<CIN * COUT / 64, 256>>>(weights, Dm);

    // (2) Stage 1: x_hat partials = x @ wbases  (split-K=16 -> 256 CTAs)
    gemm_tb<<<dim3(MODES / NT_, SPLIT1, B_), NTHR, TB_SMEM>>>(
        x, wbases, (float*)p_part, (NPTS / SPLIT1) / KC);   // 8 chunks

    // (3) split-K reduce (coalesced float4)
    k1_reduce<<<(B_ * CIN * MODES / 4) / 256, 256>>>();

    // (4) stage-2 partials (coalesced, 256 CTAs)  [profiled launch]
    k2b_part<<<dim3(COUT / 4, IGRP), 256>>>();

    // (5) stage-2 final reduce
    k2b_red2<<<(B_ * COUT * MODES / 4) / 256, 256>>>();

    // (6) Stage 3: y = y_hat @ bases^T  (512 CTAs)
    gemm_nt<<<dim3(NPTS / NT_, 1, B_), NTHR, NT_SMEM>>>(
        (const float*)p_yhat, bases, y,
        MODES, MODES, NPTS,
        (long)COUT * MODES, (long)NPTS * MODES, (long)CIN * NPTS,
        MODES / KC);                                        // 4 chunks
}